// round 4
// baseline (speedup 1.0000x reference)
#include <cuda_runtime.h>

typedef unsigned long long ull;

#define NTOT 51840000   // 405*80*80*20

__device__ float g_mask1[6400];
__device__ float g_mask2[6400];

__global__ void mask_prep(const float* __restrict__ a1, const float* __restrict__ a2)
{
    int p = blockIdx.x * blockDim.x + threadIdx.x;
    if (p < 6400) {
        float s1 = 0.f, s2 = 0.f;
        const float* p1 = a1 + p * 20;
        const float* p2 = a2 + p * 20;
        #pragma unroll
        for (int z = 0; z < 20; ++z) { s1 += p1[z]; s2 += p2[z]; }
        g_mask1[p] = fminf(fmaxf(s1, 0.f), 1.f);
        g_mask2[p] = fminf(fmaxf(s2, 0.f), 1.f);
    }
}

__device__ __forceinline__ void unpack2(ull v, float& lo, float& hi) {
    asm("mov.b64 {%0, %1}, %2;" : "=f"(lo), "=f"(hi) : "l"(v));
}
__device__ __forceinline__ void fma2(ull& d, ull a, ull b) {
    asm("fma.rn.f32x2 %0, %1, %2, %0;" : "+l"(d) : "l"(a), "l"(b));
}
// (hi32(a), lo32(b)) as a 64-bit pair
__device__ __forceinline__ ull shiftpair(ull a, ull b) {
    ull r;
    asm("{\n\t.reg .b32 alo, ahi, blo, bhi;\n\t"
        "mov.b64 {alo, ahi}, %1;\n\t"
        "mov.b64 {blo, bhi}, %2;\n\t"
        "mov.b64 %0, {ahi, blo};\n\t}"
        : "=l"(r) : "l"(a), "l"(b));
    return r;
}

// block: 240 threads, tid = zq + 5*x2c + 80*djg  (zq fastest -> coalesced stores/LDG)
// grid : (x2b 6, y 80, di 9); dj = djg*3 + jl, x = x2g + 4 - dj
// smem : f2s [c16][x2 16][13 quads] float4; quad n holds s=4n..4n+3, s=z+2 (zero-padded)
//        stride 13 (mod 8 = 5) => conflict-free LDS under zq-fast lane order
__global__ void __launch_bounds__(240, 3) corr_kernel(
    const float* __restrict__ f1, const float* __restrict__ f2, float* __restrict__ out)
{
    extern __shared__ float smem[];
    float* f2s = smem;   // 16*16*13 quads = 53248 B

    const int x2b  = blockIdx.x;
    const int y    = blockIdx.y;
    const int di   = blockIdx.z;
    const int x2g0 = x2b * 16 - 4;
    const int y2   = y + di - 4;
    const bool yok = ((unsigned)y2 < 80u);
    const int tid  = threadIdx.x;

    const int zq  = tid % 5;
    const int x2c = (tid / 5) & 15;
    const int djg = tid / 80;
    const int x2g = x2g0 + x2c;

    // clamped f1 x-offsets per jl (OOB acc is garbage but never stored)
    int xa[3];
    #pragma unroll
    for (int jl = 0; jl < 3; ++jl) {
        int x = x2g + 4 - (djg * 3 + jl);
        xa[jl] = min(max(x, 0), 79);
    }

    ull acc[30];
    #pragma unroll
    for (int i = 0; i < 30; ++i) acc[i] = 0ull;

    #pragma unroll
    for (int phase = 0; phase < 2; ++phase) {
        if (phase) __syncthreads();
        // ---- f2 smem fill: 16 channels x 16 x2 columns ----
        if (yok) {
            const float* g2 = f2 + phase * 16 * 128000 + y2 * 1600;
            for (int idx = tid; idx < 256; idx += 240) {
                int c   = idx >> 4;
                int x2l = idx & 15;
                int x2  = x2g0 + x2l;
                float* dst = f2s + ((c * 16 + x2l) * 13) * 4;
                if ((unsigned)x2 < 80u) {
                    const float* src = g2 + c * 128000 + x2 * 20;
                    *(float2*)dst = make_float2(0.f, 0.f);             // s 0,1
                    #pragma unroll
                    for (int m = 0; m < 5; ++m) {
                        float4 v = *(const float4*)(src + 4 * m);      // z 4m..4m+3
                        *(float2*)(dst + m * 4 + 2)   = make_float2(v.x, v.y);
                        *(float2*)(dst + (m + 1) * 4) = make_float2(v.z, v.w);
                    }
                    *(float2*)(dst + 22) = make_float2(0.f, 0.f);      // s 22,23
                } else {
                    #pragma unroll
                    for (int n = 0; n < 6; ++n)
                        *(float4*)(dst + n * 4) = make_float4(0.f, 0.f, 0.f, 0.f);
                }
            }
        }
        __syncthreads();
        // ---- accumulate 16 channels ----
        if (yok) {
            const float* f1c = f1 + phase * 16 * 128000 + y * 1600 + 4 * zq;
            const ulonglong2* bq =
                (const ulonglong2*)((const float4*)f2s + x2c * 13 + zq);
            #pragma unroll 4
            for (int cl = 0; cl < 16; ++cl) {
                ulonglong2 B0 = ((const ulonglong2*)((const float4*)bq + cl * 208))[0];
                ulonglong2 B4 = ((const ulonglong2*)((const float4*)bq + cl * 208 + 1))[0];
                // windows: P0=B0.x P2=B0.y P4=B4.x P6=B4.y (free)
                ull P1 = shiftpair(B0.x, B0.y);
                ull P3 = shiftpair(B0.y, B4.x);
                ull P5 = shiftpair(B4.x, B4.y);
                #pragma unroll
                for (int jl = 0; jl < 3; ++jl) {
                    ulonglong2 av = *(const ulonglong2*)(f1c + cl * 128000 + xa[jl] * 20);
                    ull a01 = av.x, a23 = av.y;
                    ull* A = acc + jl * 10;
                    fma2(A[0], a01, B0.x); fma2(A[1], a23, B0.y);   // dk=0
                    fma2(A[2], a01, P1  ); fma2(A[3], a23, P3  );   // dk=1
                    fma2(A[4], a01, B0.y); fma2(A[5], a23, B4.x);   // dk=2
                    fma2(A[6], a01, P3  ); fma2(A[7], a23, P5  );   // dk=3
                    fma2(A[8], a01, B4.x); fma2(A[9], a23, B4.y);   // dk=4
                }
            }
        }
    }

    // ---- epilogue: coalesced stores (z-fastest across lanes) ----
    {
        const bool x2ok = ((unsigned)x2g < 80u);
        const bool spin = yok && x2ok;
        const float m2v = spin ? g_mask2[y2 * 80 + x2g] : 1.f;
        const float inv = 1.f / 32.f;
        #pragma unroll
        for (int jl = 0; jl < 3; ++jl) {
            const int dj = djg * 3 + jl;
            const int x  = x2g + 4 - dj;
            if ((unsigned)x < 80u) {
                const float m1  = g_mask1[y * 80 + x];
                const float mIn = m1 * m2v;
                #pragma unroll
                for (int dk = 0; dk < 5; ++dk) {
                    const int t = dk * 81 + di * 9 + dj;
                    const int base = t * 128000 + y * 1600 + x * 20 + 4 * zq;
                    float4 cv;
                    unpack2(acc[jl * 10 + dk * 2 + 0], cv.x, cv.y);
                    unpack2(acc[jl * 10 + dk * 2 + 1], cv.z, cv.w);
                    cv.x *= inv; cv.y *= inv; cv.z *= inv; cv.w *= inv;
                    *(float4*)(out + base) = cv;
                    float4 mv;
                    {
                        float* mp = (float*)&mv;
                        #pragma unroll
                        for (int zl = 0; zl < 4; ++zl) {
                            int z2 = 4 * zq + zl + dk - 2;
                            mp[zl] = (spin && (unsigned)z2 < 20u) ? mIn : m1;
                        }
                    }
                    *(float4*)(out + NTOT + base) = mv;
                }
            }
        }
    }
}

extern "C" void kernel_launch(void* const* d_in, const int* in_sizes, int n_in,
                              void* d_out, int out_size)
{
    (void)in_sizes; (void)n_in; (void)out_size;
    const float* f1 = (const float*)d_in[0];
    const float* a1 = (const float*)d_in[1];
    const float* f2 = (const float*)d_in[2];
    const float* a2 = (const float*)d_in[3];
    float* out = (float*)d_out;

    cudaFuncSetAttribute(corr_kernel, cudaFuncAttributeMaxDynamicSharedMemorySize, 53248);

    mask_prep<<<25, 256>>>(a1, a2);
    corr_kernel<<<dim3(6, 80, 9), 240, 53248>>>(f1, f2, out);
}

// round 5
// speedup vs baseline: 1.7182x; 1.7182x over previous
#include <cuda_runtime.h>

typedef unsigned long long ull;

#define NTOT 51840000   // 405*80*80*20

__device__ float g_mask1[6400];
__device__ float g_mask2[6400];

__global__ void mask_prep(const float* __restrict__ a1, const float* __restrict__ a2)
{
    int p = blockIdx.x * blockDim.x + threadIdx.x;
    if (p < 6400) {
        float s1 = 0.f, s2 = 0.f;
        const float* p1 = a1 + p * 20;
        const float* p2 = a2 + p * 20;
        #pragma unroll
        for (int z = 0; z < 20; ++z) { s1 += p1[z]; s2 += p2[z]; }
        g_mask1[p] = fminf(fmaxf(s1, 0.f), 1.f);
        g_mask2[p] = fminf(fmaxf(s2, 0.f), 1.f);
    }
}

__device__ __forceinline__ void unpack2(ull v, float& lo, float& hi) {
    asm("mov.b64 {%0, %1}, %2;" : "=f"(lo), "=f"(hi) : "l"(v));
}
__device__ __forceinline__ void fma2(ull& d, ull a, ull b) {
    asm("fma.rn.f32x2 %0, %1, %2, %0;" : "+l"(d) : "l"(a), "l"(b));
}
// (hi32(a), lo32(b)) as a 64-bit pair
__device__ __forceinline__ ull shiftpair(ull a, ull b) {
    ull r;
    asm("{\n\t.reg .b32 alo, ahi, blo, bhi;\n\t"
        "mov.b64 {alo, ahi}, %1;\n\t"
        "mov.b64 {blo, bhi}, %2;\n\t"
        "mov.b64 %0, {ahi, blo};\n\t}"
        : "=l"(r) : "l"(a), "l"(b));
    return r;
}

// block: 240 threads, tid = zq + 5*x2c + 80*djg  (zq fastest -> coalesced stores)
// grid : (x2b 6, y 80, di 9); dj = djg*3 + jl, x = x2g + 4 - dj
// smem per 8-channel phase (4 phases):
//   f1s [c8][xl24][q5]  float4 = 960 quads (15360 B); x = x2g0 + xl - 4, zero-padded
//   f2s [c8][x2 16][13] float4 = 1664 quads (26624 B); quad n = s 4n..4n+3, s=z+2, zero-padded
// bank-quads: a (5*x2c+zq)%8 distinct per 8-lane phase; b (13*x2c+zq)%8 distinct
__global__ void __launch_bounds__(240, 3) corr_kernel(
    const float* __restrict__ f1, const float* __restrict__ f2, float* __restrict__ out)
{
    extern __shared__ float smem[];
    float* f1s = smem;            // 3840 floats
    float* f2s = smem + 3840;     // 6656 floats

    const int x2b  = blockIdx.x;
    const int y    = blockIdx.y;
    const int di   = blockIdx.z;
    const int x2g0 = x2b * 16 - 4;
    const int y2   = y + di - 4;
    const bool yok = ((unsigned)y2 < 80u);
    const int tid  = threadIdx.x;

    const int zq  = tid % 5;
    const int x2c = (tid / 5) & 15;
    const int djg = tid / 80;
    const int x2g = x2g0 + x2c;

    ull acc[30];
    #pragma unroll
    for (int i = 0; i < 30; ++i) acc[i] = 0ull;

    #pragma unroll
    for (int phase = 0; phase < 4; ++phase) {
        if (phase) __syncthreads();
        if (yok) {
            // ---- f1 fill: 8 channels x 24 xl x 5 quads ----
            const float* g1 = f1 + phase * 8 * 128000 + y * 1600;
            for (int idx = tid; idx < 960; idx += 240) {
                int c  = idx / 120;
                int r  = idx - c * 120;
                int xl = r / 5;
                int q  = r - xl * 5;
                int xg = x2g0 + xl - 4;
                float4 v = make_float4(0.f, 0.f, 0.f, 0.f);
                if ((unsigned)xg < 80u)
                    v = *(const float4*)(g1 + c * 128000 + xg * 20 + 4 * q);
                ((float4*)f1s)[(c * 24 + xl) * 5 + q] = v;
            }
            // ---- f2 fill: 8 channels x 16 x2 cols, depth-padded (s = z+2) ----
            const float* g2 = f2 + phase * 8 * 128000 + y2 * 1600;
            for (int idx = tid - 128; (unsigned)idx < 128u; ++idx) { /*nop*/ }
            for (int idx = tid; idx < 128; idx += 240) {
                int c   = idx >> 4;
                int x2l = idx & 15;
                int x2  = x2g0 + x2l;
                float* dst = f2s + ((c * 16 + x2l) * 13) * 4;
                if ((unsigned)x2 < 80u) {
                    const float* src = g2 + c * 128000 + x2 * 20;
                    *(float2*)dst = make_float2(0.f, 0.f);             // s 0,1
                    #pragma unroll
                    for (int m = 0; m < 5; ++m) {
                        float4 v = *(const float4*)(src + 4 * m);      // z 4m..4m+3
                        *(float2*)(dst + m * 4 + 2)   = make_float2(v.x, v.y);
                        *(float2*)(dst + (m + 1) * 4) = make_float2(v.z, v.w);
                    }
                    *(float2*)(dst + 22) = make_float2(0.f, 0.f);      // s 22,23
                } else {
                    #pragma unroll
                    for (int n = 0; n < 6; ++n)
                        *(float4*)(dst + n * 4) = make_float4(0.f, 0.f, 0.f, 0.f);
                }
            }
        }
        __syncthreads();
        if (yok) {
            #pragma unroll 2
            for (int cl = 0; cl < 8; ++cl) {
                const ulonglong2* bq = (const ulonglong2*)
                    ((const float4*)f2s + (cl * 16 + x2c) * 13 + zq);
                ulonglong2 B0 = bq[0];
                ull B4x = ((const ull*)bq)[2];
                ull B4y = ((const ull*)bq)[3];
                // windows: P0=B0.x P2=B0.y P4=B4x P6=B4y
                ull P1 = shiftpair(B0.x, B0.y);
                ull P3 = shiftpair(B0.y, B4x);
                ull P5 = shiftpair(B4x, B4y);
                #pragma unroll
                for (int jl = 0; jl < 3; ++jl) {
                    int xl = x2c + 8 - djg * 3 - jl;
                    ulonglong2 av = *(const ulonglong2*)
                        ((const float4*)f1s + (cl * 24 + xl) * 5 + zq);
                    ull a01 = av.x, a23 = av.y;
                    ull* A = acc + jl * 10;
                    fma2(A[0], a01, B0.x); fma2(A[1], a23, B0.y);   // dk=0
                    fma2(A[2], a01, P1  ); fma2(A[3], a23, P3  );   // dk=1
                    fma2(A[4], a01, B0.y); fma2(A[5], a23, B4x );   // dk=2
                    fma2(A[6], a01, P3  ); fma2(A[7], a23, P5  );   // dk=3
                    fma2(A[8], a01, B4x ); fma2(A[9], a23, B4y );   // dk=4
                }
            }
        }
    }

    // ---- epilogue: coalesced stores (z-fastest across lanes) ----
    {
        const bool x2ok = ((unsigned)x2g < 80u);
        const bool spin = yok && x2ok;
        const float m2v = spin ? g_mask2[y2 * 80 + x2g] : 1.f;
        const float inv = 1.f / 32.f;
        #pragma unroll
        for (int jl = 0; jl < 3; ++jl) {
            const int dj = djg * 3 + jl;
            const int x  = x2g + 4 - dj;
            if ((unsigned)x < 80u) {
                const float m1  = g_mask1[y * 80 + x];
                const float mIn = m1 * m2v;
                #pragma unroll
                for (int dk = 0; dk < 5; ++dk) {
                    const int t = dk * 81 + di * 9 + dj;
                    const int base = t * 128000 + y * 1600 + x * 20 + 4 * zq;
                    float4 cv;
                    unpack2(acc[jl * 10 + dk * 2 + 0], cv.x, cv.y);
                    unpack2(acc[jl * 10 + dk * 2 + 1], cv.z, cv.w);
                    cv.x *= inv; cv.y *= inv; cv.z *= inv; cv.w *= inv;
                    *(float4*)(out + base) = cv;
                    float4 mv;
                    {
                        float* mp = (float*)&mv;
                        #pragma unroll
                        for (int zl = 0; zl < 4; ++zl) {
                            int z2 = 4 * zq + zl + dk - 2;
                            mp[zl] = (spin && (unsigned)z2 < 20u) ? mIn : m1;
                        }
                    }
                    *(float4*)(out + NTOT + base) = mv;
                }
            }
        }
    }
}

extern "C" void kernel_launch(void* const* d_in, const int* in_sizes, int n_in,
                              void* d_out, int out_size)
{
    (void)in_sizes; (void)n_in; (void)out_size;
    const float* f1 = (const float*)d_in[0];
    const float* a1 = (const float*)d_in[1];
    const float* f2 = (const float*)d_in[2];
    const float* a2 = (const float*)d_in[3];
    float* out = (float*)d_out;

    cudaFuncSetAttribute(corr_kernel, cudaFuncAttributeMaxDynamicSharedMemorySize, 41984);

    mask_prep<<<25, 256>>>(a1, a2);
    corr_kernel<<<dim3(6, 80, 9), 240, 41984>>>(f1, f2, out);
}

// round 6
// speedup vs baseline: 1.9067x; 1.1097x over previous
#include <cuda_runtime.h>

typedef unsigned long long ull;

#define NTOT 51840000   // 405*80*80*20

__device__ float g_mask1[6400];
__device__ float g_mask2[6400];

__global__ void mask_prep(const float* __restrict__ a1, const float* __restrict__ a2)
{
    int p = blockIdx.x * blockDim.x + threadIdx.x;
    if (p < 6400) {
        float s1 = 0.f, s2 = 0.f;
        const float* p1 = a1 + p * 20;
        const float* p2 = a2 + p * 20;
        #pragma unroll
        for (int z = 0; z < 20; ++z) { s1 += p1[z]; s2 += p2[z]; }
        g_mask1[p] = fminf(fmaxf(s1, 0.f), 1.f);
        g_mask2[p] = fminf(fmaxf(s2, 0.f), 1.f);
    }
}

__device__ __forceinline__ void unpack2(ull v, float& lo, float& hi) {
    asm("mov.b64 {%0, %1}, %2;" : "=f"(lo), "=f"(hi) : "l"(v));
}
__device__ __forceinline__ void fma2(ull& d, ull a, ull b) {
    asm("fma.rn.f32x2 %0, %1, %2, %0;" : "+l"(d) : "l"(a), "l"(b));
}
__device__ __forceinline__ ull shiftpair(ull a, ull b) {
    ull r;
    asm("{\n\t.reg .b32 alo, ahi, blo, bhi;\n\t"
        "mov.b64 {alo, ahi}, %1;\n\t"
        "mov.b64 {blo, bhi}, %2;\n\t"
        "mov.b64 %0, {ahi, blo};\n\t}"
        : "=l"(r) : "l"(a), "l"(b));
    return r;
}
__device__ __forceinline__ void cp16(unsigned dst, const void* src) {
    asm volatile("cp.async.cg.shared.global [%0], [%1], 16;" :: "r"(dst), "l"(src));
}
__device__ __forceinline__ void cp_commit() {
    asm volatile("cp.async.commit_group;" ::: "memory");
}
template<int N> __device__ __forceinline__ void cp_wait() {
    asm volatile("cp.async.wait_group %0;" :: "n"(N) : "memory");
}

// block: 240 threads, tid = zq + 5*x2c + 80*djg (zq fastest -> coalesced stores)
// grid : (x2b 6, y 80, di 9); dj = djg*3 + jl, x = x2g + 4 - dj
// 8 phases x 4 channels, double-buffered cp.async:
//  f1 buf: [c4][xl24][q5] quads (480 q = 7680 B each); xg = x2g0 + xl - 4, zero-pad
//  f2 buf: [c4][x2 16][13 quads] (832 q = 13312 B each); guard quads 0 & 6 = zero,
//          quads 1..5 = z 0..19 (unshifted), quads 7..12 unused
// total smem = 2*7680 + 2*13312 = 41984 B -> 3 blocks/SM
#define F1B 7680
#define F2B 13312
#define F2BASE 15360
#define CADV 512000   // 4 channels * 128000 floats

__global__ void __launch_bounds__(240, 3) corr_kernel(
    const float* __restrict__ f1, const float* __restrict__ f2, float* __restrict__ out)
{
    extern __shared__ float smem[];
    const unsigned sb = (unsigned)__cvta_generic_to_shared(smem);

    const int x2b  = blockIdx.x;
    const int y    = blockIdx.y;
    const int di   = blockIdx.z;
    const int x2g0 = x2b * 16 - 4;
    const int y2   = y + di - 4;
    const bool yok = ((unsigned)y2 < 80u);
    const int tid  = threadIdx.x;

    const int zq  = tid % 5;
    const int x2c = (tid / 5) & 15;
    const int djg = tid / 80;
    const int x2g = x2g0 + x2c;

    // ---- precompute fill assignments (src offsets in floats; <0 = skip) ----
    int f1off[2]; unsigned f1dst[2];
    #pragma unroll
    for (int k = 0; k < 2; ++k) {
        int idx = tid + 240 * k;            // 0..479 quads
        int c  = idx / 120;
        int r  = idx - c * 120;
        int xl = r / 5;
        int q  = r - xl * 5;
        int xg = x2g0 + xl - 4;
        f1dst[k] = sb + idx * 16;
        f1off[k] = (yok && (unsigned)xg < 80u)
                   ? (c * 128000 + y * 1600 + xg * 20 + 4 * q) : (int)0x80000000;
    }
    int f2off[2]; unsigned f2dst[2];
    #pragma unroll
    for (int k = 0; k < 2; ++k) {
        int j = tid + 240 * k;              // 0..319 copies
        int i = j / 5;
        int m = j - i * 5;
        int c   = i >> 4;
        int x2l = i & 15;
        int x2  = x2g0 + x2l;
        f2dst[k] = sb + F2BASE + ((c * 16 + x2l) * 13 + 1 + m) * 16;
        f2off[k] = (j < 320 && yok && (unsigned)x2 < 80u)
                   ? (c * 128000 + y2 * 1600 + x2 * 20 + 4 * m) : (int)0x80000000;
    }

    // ---- zero both buffers (guards / OOB stay zero; cp.async writes valid only) ----
    {
        float4 z4 = make_float4(0.f, 0.f, 0.f, 0.f);
        for (int i = tid; i < 2624; i += 240) ((float4*)smem)[i] = z4;
    }
    __syncthreads();

    // ---- prologue: issue phase 0 into buffer 0 ----
    if (f1off[0] >= 0) cp16(f1dst[0], f1 + f1off[0]);
    if (f1off[1] >= 0) cp16(f1dst[1], f1 + f1off[1]);
    if (f2off[0] >= 0) cp16(f2dst[0], f2 + f2off[0]);
    if (f2off[1] >= 0) cp16(f2dst[1], f2 + f2off[1]);
    cp_commit();

    ull acc[30];
    #pragma unroll
    for (int i = 0; i < 30; ++i) acc[i] = 0ull;

    const int aq0 = (x2c + 8 - djg * 3) * 5 + zq;   // f1 quad idx (jl subtracts 5)
    const int bq0 = x2c * 13 + zq;                  // f2 quad idx within channel

    #pragma unroll 2
    for (int p = 0; p < 8; ++p) {
        const int cur = p & 1;
        // issue next phase into the other buffer
        if (p < 7) {
            const int adv = (p + 1) * CADV;
            const unsigned b1 = (1 - cur) * F1B, b2 = (1 - cur) * F2B;
            if (f1off[0] >= 0) cp16(f1dst[0] + b1, f1 + f1off[0] + adv);
            if (f1off[1] >= 0) cp16(f1dst[1] + b1, f1 + f1off[1] + adv);
            if (f2off[0] >= 0) cp16(f2dst[0] + b2, f2 + f2off[0] + adv);
            if (f2off[1] >= 0) cp16(f2dst[1] + b2, f2 + f2off[1] + adv);
            cp_commit();
            cp_wait<1>();
        } else {
            cp_wait<0>();
        }
        __syncthreads();

        if (yok) {
            const float* f1b = smem + cur * (F1B / 4);
            const float* f2b = smem + (F2BASE + cur * F2B) / 4;
            #pragma unroll
            for (int cl = 0; cl < 4; ++cl) {
                const float* bp = f2b + (cl * 208 + bq0) * 4;
                ull q0hi = *(const ull*)(bp + 2);                 // z 4zq-2,4zq-1
                ulonglong2 Q1 = *(const ulonglong2*)(bp + 4);     // z 4zq..4zq+3
                ull q2lo = *(const ull*)(bp + 8);                 // z 4zq+4,4zq+5
                ull P1 = shiftpair(q0hi, Q1.x);
                ull P3 = shiftpair(Q1.x, Q1.y);
                ull P5 = shiftpair(Q1.y, q2lo);
                #pragma unroll
                for (int jl = 0; jl < 3; ++jl) {
                    ulonglong2 av = *(const ulonglong2*)(f1b + (cl * 120 + aq0 - 5 * jl) * 4);
                    ull a01 = av.x, a23 = av.y;
                    ull* A = acc + jl * 10;
                    fma2(A[0], a01, q0hi); fma2(A[1], a23, Q1.x);   // dk=0
                    fma2(A[2], a01, P1  ); fma2(A[3], a23, P3  );   // dk=1
                    fma2(A[4], a01, Q1.x); fma2(A[5], a23, Q1.y);   // dk=2
                    fma2(A[6], a01, P3  ); fma2(A[7], a23, P5  );   // dk=3
                    fma2(A[8], a01, Q1.y); fma2(A[9], a23, q2lo);   // dk=4
                }
            }
        }
        __syncthreads();   // protect buf[cur] before next iteration's cp.async issue
    }

    // ---- epilogue: coalesced stores (z-fastest across lanes) ----
    {
        const bool x2ok = ((unsigned)x2g < 80u);
        const bool spin = yok && x2ok;
        const float m2v = spin ? g_mask2[y2 * 80 + x2g] : 1.f;
        const float inv = 1.f / 32.f;
        #pragma unroll
        for (int jl = 0; jl < 3; ++jl) {
            const int dj = djg * 3 + jl;
            const int x  = x2g + 4 - dj;
            if ((unsigned)x < 80u) {
                const float m1  = g_mask1[y * 80 + x];
                const float mIn = m1 * m2v;
                #pragma unroll
                for (int dk = 0; dk < 5; ++dk) {
                    const int t = dk * 81 + di * 9 + dj;
                    const int base = t * 128000 + y * 1600 + x * 20 + 4 * zq;
                    float4 cv;
                    unpack2(acc[jl * 10 + dk * 2 + 0], cv.x, cv.y);
                    unpack2(acc[jl * 10 + dk * 2 + 1], cv.z, cv.w);
                    cv.x *= inv; cv.y *= inv; cv.z *= inv; cv.w *= inv;
                    *(float4*)(out + base) = cv;
                    float4 mv;
                    {
                        float* mp = (float*)&mv;
                        #pragma unroll
                        for (int zl = 0; zl < 4; ++zl) {
                            int z2 = 4 * zq + zl + dk - 2;
                            mp[zl] = (spin && (unsigned)z2 < 20u) ? mIn : m1;
                        }
                    }
                    *(float4*)(out + NTOT + base) = mv;
                }
            }
        }
    }
}

extern "C" void kernel_launch(void* const* d_in, const int* in_sizes, int n_in,
                              void* d_out, int out_size)
{
    (void)in_sizes; (void)n_in; (void)out_size;
    const float* f1 = (const float*)d_in[0];
    const float* a1 = (const float*)d_in[1];
    const float* f2 = (const float*)d_in[2];
    const float* a2 = (const float*)d_in[3];
    float* out = (float*)d_out;

    cudaFuncSetAttribute(corr_kernel, cudaFuncAttributeMaxDynamicSharedMemorySize, 41984);

    mask_prep<<<25, 256>>>(a1, a2);
    corr_kernel<<<dim3(6, 80, 9), 240, 41984>>>(f1, f2, out);
}